// round 1
// baseline (speedup 1.0000x reference)
#include <cuda_runtime.h>
#include <cuda_bf16.h>

// Problem constants
#define B 4
#define N 256
#define F 128
#define H 256

// Scratch (allocation-free rule: __device__ globals)
__device__ float g_ub[B * H];          // u[b,h] + b1[h]
__device__ float g_A[B * N * H];       // relu(x_i) @ W1_i + ub  (ub folded in)
__device__ float g_C[B * N * H];       // relu(x_j) @ W1_j

// ---------------------------------------------------------------------------
// Kernel 1: pooled context.  grid(B), block(128)
//   mean over nodes -> @W_pool -> relu -> @W1[0:F] -> +b1 -> g_ub
// ---------------------------------------------------------------------------
__global__ void k_pool(const float* __restrict__ x,
                       const float* __restrict__ Wp,
                       const float* __restrict__ W1,
                       const float* __restrict__ b1) {
    int b = blockIdx.x;
    int tid = threadIdx.x;              // 0..127
    __shared__ float m[F];
    __shared__ float r[F];

    // mean over n of x[b, n, tid]  (coalesced across tid)
    float s = 0.f;
    const float* xb = x + b * N * F;
    for (int n = 0; n < N; n++) s += xb[n * F + tid];
    m[tid] = s * (1.0f / N);
    __syncthreads();

    // h_pool[tid] = sum_f m[f] * Wp[f, tid]; relu
    float hp = 0.f;
    #pragma unroll 4
    for (int f = 0; f < F; f++) hp += m[f] * Wp[f * F + tid];
    r[tid] = fmaxf(hp, 0.f);
    __syncthreads();

    // u[h] = sum_f r[f] * W1[f, h], h in 0..255 (2 per thread)
    #pragma unroll
    for (int k = 0; k < 2; k++) {
        int h = tid + 128 * k;
        float u = 0.f;
        #pragma unroll 4
        for (int f = 0; f < F; f++) u += r[f] * W1[f * H + h];
        g_ub[b * H + h] = u + b1[h];
    }
}

// ---------------------------------------------------------------------------
// Kernel 2: per-node GEMMs.  grid(B*N/8 = 128), block(256)
//   8 rows per block; each thread owns one output column h (0..255) and
//   8 A-accumulators + 8 C-accumulators.
// ---------------------------------------------------------------------------
__global__ void k_nodegemm(const float* __restrict__ x,
                           const float* __restrict__ W1) {
    const int ROWS = 8;
    int row0 = blockIdx.x * ROWS;        // global row in [0, B*N)
    int b = row0 / N;
    int h = threadIdx.x;                 // 0..255

    __shared__ float rx[ROWS][F];
    for (int idx = threadIdx.x; idx < ROWS * F; idx += blockDim.x) {
        int r = idx / F, f = idx % F;
        rx[r][f] = fmaxf(x[(row0 + r) * F + f], 0.f);
    }
    __syncthreads();

    float accA[ROWS], accC[ROWS];
    #pragma unroll
    for (int r = 0; r < ROWS; r++) { accA[r] = 0.f; accC[r] = 0.f; }

    const float* W1a = W1 + (size_t)F * H;       // rows [F, 2F)
    const float* W1c = W1 + (size_t)(2 * F) * H; // rows [2F, 3F)

    #pragma unroll 4
    for (int f = 0; f < F; f++) {
        float wa = W1a[f * H + h];   // coalesced LDG across threads
        float wc = W1c[f * H + h];
        #pragma unroll
        for (int r = 0; r < ROWS; r++) {
            float v = rx[r][f];      // smem broadcast
            accA[r] += v * wa;
            accC[r] += v * wc;
        }
    }

    float ub = g_ub[b * H + h];
    #pragma unroll
    for (int r = 0; r < ROWS; r++) {
        g_A[(row0 + r) * H + h] = accA[r] + ub;
        g_C[(row0 + r) * H + h] = accC[r];
    }
}

// ---------------------------------------------------------------------------
// Kernel 3: pairwise fused readout.  grid(16,16,B), block(256)
//   16x16 output tile per block; thread (ti,tj) computes one (i,j).
//   out[b,i,j] = sum_h relu(A[b,i,h] + C[b,j,h]) * W2[h] + b2
// ---------------------------------------------------------------------------
#define TS 16
#define HPAD 260   // stride 260 floats: 8-lane float4 phases tile all 32 banks

__global__ void k_pairwise(const float* __restrict__ W2,
                           const float* __restrict__ b2,
                           float* __restrict__ out) {
    __shared__ __align__(16) float As[TS][HPAD];
    __shared__ __align__(16) float Cs[TS][HPAD];
    __shared__ __align__(16) float w2s[H];

    int b  = blockIdx.z;
    int i0 = blockIdx.y * TS;
    int j0 = blockIdx.x * TS;
    int tid = threadIdx.x;

    // Load tiles (float4, coalesced)
    {
        const float4* Ag = (const float4*)(g_A + ((size_t)(b * N + i0)) * H);
        const float4* Cg = (const float4*)(g_C + ((size_t)(b * N + j0)) * H);
        for (int idx = tid; idx < TS * (H / 4); idx += 256) {
            int r = idx >> 6;          // /64
            int q = idx & 63;
            ((float4*)&As[r][0])[q] = Ag[r * (H / 4) + q];
            ((float4*)&Cs[r][0])[q] = Cg[r * (H / 4) + q];
        }
        if (tid < H) w2s[tid] = W2[tid];
    }
    __syncthreads();

    int tj = tid & (TS - 1);
    int ti = tid >> 4;
    float b2v = b2[0];

    const float4* ap = (const float4*)&As[ti][0];
    const float4* cp = (const float4*)&Cs[tj][0];
    const float4* wp = (const float4*)&w2s[0];

    float sum = 0.f;
    #pragma unroll 8
    for (int q = 0; q < H / 4; q++) {
        float4 a = ap[q];
        float4 c = cp[q];
        float4 w = wp[q];
        sum += fmaxf(a.x + c.x, 0.f) * w.x;
        sum += fmaxf(a.y + c.y, 0.f) * w.y;
        sum += fmaxf(a.z + c.z, 0.f) * w.z;
        sum += fmaxf(a.w + c.w, 0.f) * w.w;
    }

    out[((size_t)(b * N + i0 + ti)) * N + (j0 + tj)] = sum + b2v;
}

// ---------------------------------------------------------------------------
extern "C" void kernel_launch(void* const* d_in, const int* in_sizes, int n_in,
                              void* d_out, int out_size) {
    const float* x   = (const float*)d_in[0];  // [B,N,F]
    const float* Wp  = (const float*)d_in[1];  // [F,F]
    const float* W1  = (const float*)d_in[2];  // [3F,H]
    const float* b1  = (const float*)d_in[3];  // [H]
    const float* W2  = (const float*)d_in[4];  // [H,1]
    const float* b2  = (const float*)d_in[5];  // [1]
    float* out = (float*)d_out;                // [B,N,N,1]

    k_pool<<<B, 128>>>(x, Wp, W1, b1);
    k_nodegemm<<<(B * N) / 8, 256>>>(x, W1);
    k_pairwise<<<dim3(N / TS, N / TS, B), 256>>>(W2, b2, out);
}

// round 2
// speedup vs baseline: 1.4765x; 1.4765x over previous
#include <cuda_runtime.h>
#include <cuda_bf16.h>

// Problem constants
#define B 4
#define N 256
#define F 128
#define H 256

// Scratch (allocation-free rule: __device__ globals)
__device__ float g_ub[B * H];          // u[b,h] + b1[h]
__device__ float g_A[B * N * H];       // relu(x_i) @ W1_i + ub  (ub folded in)
__device__ float g_C[B * N * H];       // relu(x_j) @ W1_j

// ---------------------------------------------------------------------------
// Kernel 1: pooled context.  grid(B), block(1024)
//   mean over nodes -> @W_pool -> relu -> @W1[0:F] -> +b1 -> g_ub
//   Every dot product is split across thread-groups so each thread issues
//   a short fully-unrolled run of INDEPENDENT loads (high MLP), instead of
//   a 128-256 iteration latency chain.
// ---------------------------------------------------------------------------
__global__ void __launch_bounds__(1024) k_pool(
        const float* __restrict__ x,
        const float* __restrict__ Wp,
        const float* __restrict__ W1,
        const float* __restrict__ b1) {
    int b = blockIdx.x;
    int tid = threadIdx.x;              // 0..1023

    __shared__ float part8[8][F];       // 8-way partials (phases 1,2)
    __shared__ float part4[4][H];       // 4-way partials (phase 3)
    __shared__ float m[F];
    __shared__ float r[F];

    const float* xb = x + b * N * F;

    // ---- Phase 1: column mean.  thread = (g, f); group g sums 32 nodes ----
    {
        int f = tid & (F - 1);
        int g = tid >> 7;               // 0..7
        float s = 0.f;
        #pragma unroll
        for (int n = 0; n < 32; n++)
            s += xb[(g * 32 + n) * F + f];   // coalesced, independent
        part8[g][f] = s;
    }
    __syncthreads();
    if (tid < F) {
        float t = 0.f;
        #pragma unroll
        for (int g = 0; g < 8; g++) t += part8[g][tid];
        m[tid] = t * (1.0f / N);
    }
    __syncthreads();

    // ---- Phase 2: hp[f] = relu(sum_fin m[fin] * Wp[fin, f]) ----
    {
        int f = tid & (F - 1);
        int g = tid >> 7;               // 0..7, 16 terms each
        float s = 0.f;
        #pragma unroll
        for (int k = 0; k < 16; k++) {
            int fin = g * 16 + k;
            s += m[fin] * Wp[fin * F + f];
        }
        part8[g][f] = s;
    }
    __syncthreads();
    if (tid < F) {
        float t = 0.f;
        #pragma unroll
        for (int g = 0; g < 8; g++) t += part8[g][tid];
        r[tid] = fmaxf(t, 0.f);
    }
    __syncthreads();

    // ---- Phase 3: u[h] = sum_f r[f] * W1[f, h] + b1[h] ----
    {
        int h = tid & (H - 1);
        int g = tid >> 8;               // 0..3, 32 terms each
        float s = 0.f;
        #pragma unroll
        for (int k = 0; k < 32; k++) {
            int fin = g * 32 + k;
            s += r[fin] * W1[fin * H + h];
        }
        part4[g][h] = s;
    }
    __syncthreads();
    if (tid < H) {
        float t = 0.f;
        #pragma unroll
        for (int g = 0; g < 4; g++) t += part4[g][tid];
        g_ub[b * H + tid] = t + b1[tid];
    }
}

// ---------------------------------------------------------------------------
// Kernel 2: per-node GEMMs.  grid(B*N/8 = 128), block(256)
//   8 rows per block; each thread owns one output column h (0..255) and
//   8 A-accumulators + 8 C-accumulators.
// ---------------------------------------------------------------------------
__global__ void k_nodegemm(const float* __restrict__ x,
                           const float* __restrict__ W1) {
    const int ROWS = 8;
    int row0 = blockIdx.x * ROWS;        // global row in [0, B*N)
    int b = row0 / N;
    int h = threadIdx.x;                 // 0..255

    __shared__ float rx[ROWS][F];
    for (int idx = threadIdx.x; idx < ROWS * F; idx += blockDim.x) {
        int r = idx / F, f = idx % F;
        rx[r][f] = fmaxf(x[(row0 + r) * F + f], 0.f);
    }
    __syncthreads();

    float accA[ROWS], accC[ROWS];
    #pragma unroll
    for (int r = 0; r < ROWS; r++) { accA[r] = 0.f; accC[r] = 0.f; }

    const float* W1a = W1 + (size_t)F * H;       // rows [F, 2F)
    const float* W1c = W1 + (size_t)(2 * F) * H; // rows [2F, 3F)

    #pragma unroll 4
    for (int f = 0; f < F; f++) {
        float wa = W1a[f * H + h];   // coalesced LDG across threads
        float wc = W1c[f * H + h];
        #pragma unroll
        for (int r = 0; r < ROWS; r++) {
            float v = rx[r][f];      // smem broadcast
            accA[r] += v * wa;
            accC[r] += v * wc;
        }
    }

    float ub = g_ub[b * H + h];
    #pragma unroll
    for (int r = 0; r < ROWS; r++) {
        g_A[(row0 + r) * H + h] = accA[r] + ub;
        g_C[(row0 + r) * H + h] = accC[r];
    }
}

// ---------------------------------------------------------------------------
// Kernel 3: pairwise fused readout.  grid(16,16,B), block(256)
//   16x16 output tile per block; thread (ti,tj) computes one (i,j).
//   out[b,i,j] = sum_h relu(A[b,i,h] + C[b,j,h]) * W2[h] + b2
// ---------------------------------------------------------------------------
#define TS 16
#define HPAD 260   // stride 260 floats: 8-lane float4 phases tile all 32 banks

__global__ void k_pairwise(const float* __restrict__ W2,
                           const float* __restrict__ b2,
                           float* __restrict__ out) {
    __shared__ __align__(16) float As[TS][HPAD];
    __shared__ __align__(16) float Cs[TS][HPAD];
    __shared__ __align__(16) float w2s[H];

    int b  = blockIdx.z;
    int i0 = blockIdx.y * TS;
    int j0 = blockIdx.x * TS;
    int tid = threadIdx.x;

    // Load tiles (float4, coalesced)
    {
        const float4* Ag = (const float4*)(g_A + ((size_t)(b * N + i0)) * H);
        const float4* Cg = (const float4*)(g_C + ((size_t)(b * N + j0)) * H);
        for (int idx = tid; idx < TS * (H / 4); idx += 256) {
            int r = idx >> 6;          // /64
            int q = idx & 63;
            ((float4*)&As[r][0])[q] = Ag[r * (H / 4) + q];
            ((float4*)&Cs[r][0])[q] = Cg[r * (H / 4) + q];
        }
        if (tid < H) w2s[tid] = W2[tid];
    }
    __syncthreads();

    int tj = tid & (TS - 1);
    int ti = tid >> 4;
    float b2v = b2[0];

    const float4* ap = (const float4*)&As[ti][0];
    const float4* cp = (const float4*)&Cs[tj][0];
    const float4* wp = (const float4*)&w2s[0];

    float sum = 0.f;
    #pragma unroll 8
    for (int q = 0; q < H / 4; q++) {
        float4 a = ap[q];
        float4 c = cp[q];
        float4 w = wp[q];
        sum += fmaxf(a.x + c.x, 0.f) * w.x;
        sum += fmaxf(a.y + c.y, 0.f) * w.y;
        sum += fmaxf(a.z + c.z, 0.f) * w.z;
        sum += fmaxf(a.w + c.w, 0.f) * w.w;
    }

    out[((size_t)(b * N + i0 + ti)) * N + (j0 + tj)] = sum + b2v;
}

// ---------------------------------------------------------------------------
extern "C" void kernel_launch(void* const* d_in, const int* in_sizes, int n_in,
                              void* d_out, int out_size) {
    const float* x   = (const float*)d_in[0];  // [B,N,F]
    const float* Wp  = (const float*)d_in[1];  // [F,F]
    const float* W1  = (const float*)d_in[2];  // [3F,H]
    const float* b1  = (const float*)d_in[3];  // [H]
    const float* W2  = (const float*)d_in[4];  // [H,1]
    const float* b2  = (const float*)d_in[5];  // [1]
    float* out = (float*)d_out;                // [B,N,N,1]

    k_pool<<<B, 1024>>>(x, Wp, W1, b1);
    k_nodegemm<<<(B * N) / 8, 256>>>(x, W1);
    k_pairwise<<<dim3(N / TS, N / TS, B), 256>>>(W2, b2, out);
}

// round 3
// speedup vs baseline: 2.0574x; 1.3934x over previous
#include <cuda_runtime.h>
#include <cuda_bf16.h>

// Problem constants
#define B 4
#define N 256
#define F 128
#define H 256

typedef unsigned long long ull;

// Scratch (allocation-free rule: __device__ globals)
__device__ __align__(16) float g_ub[B * H];     // u[b,h] + b1[h]
__device__ __align__(16) float g_A[B * N * H];  // relu(x_i) @ W1_i   (raw, no ub)
__device__ __align__(16) float g_C[B * N * H];  // relu(x_j) @ W1_j

// ---- packed f32x2 helpers (sm_100+) ---------------------------------------
static __device__ __forceinline__ ull add2(ull a, ull b) {
    ull d; asm("add.rn.f32x2 %0, %1, %2;" : "=l"(d) : "l"(a), "l"(b)); return d;
}
static __device__ __forceinline__ ull fma2(ull a, ull b, ull c) {
    ull d; asm("fma.rn.f32x2 %0, %1, %2, %3;" : "=l"(d) : "l"(a), "l"(b), "l"(c)); return d;
}
static __device__ __forceinline__ ull pack2(float lo, float hi) {
    ull d; asm("mov.b64 %0, {%1, %2};" : "=l"(d) : "f"(lo), "f"(hi)); return d;
}
static __device__ __forceinline__ void unpack2(ull v, float& lo, float& hi) {
    asm("mov.b64 {%0, %1}, %2;" : "=f"(lo), "=f"(hi) : "l"(v));
}
static __device__ __forceinline__ ull relu2(ull v) {
    float lo, hi; unpack2(v, lo, hi);
    return pack2(fmaxf(lo, 0.f), fmaxf(hi, 0.f));   // halves of the reg pair
}

// ---------------------------------------------------------------------------
// Kernel 1: fused nodegemm (blocks 0..127) + pool (blocks 128..131).
//   Independent because ub is folded into k_pair's A-tile load.
// ---------------------------------------------------------------------------
__global__ void __launch_bounds__(256) k_main(
        const float* __restrict__ x,
        const float* __restrict__ Wp,
        const float* __restrict__ W1,
        const float* __restrict__ b1) {
    __shared__ __align__(16) float sbuf[1024];   // 4 KB, role depends on block
    int tid = threadIdx.x;

    if (blockIdx.x < 128) {
        // ================== nodegemm: 8 rows, dual GEMM, f32x2 ==============
        const int ROWS = 8;
        int row0 = blockIdx.x * ROWS;
        int h = tid;

        // rx packed: word f*8 + r  => pairs (r, r+1) contiguous (8B)
        for (int idx = tid; idx < ROWS * F; idx += 256) {
            int r = idx >> 7, f = idx & (F - 1);
            sbuf[f * 8 + r] = fmaxf(x[(row0 + r) * F + f], 0.f);
        }
        __syncthreads();

        const ull* rxu = (const ull*)sbuf;           // [F][4] row-pairs
        const float* W1a = W1 + (size_t)F * H;       // rows [F, 2F)
        const float* W1c = W1 + (size_t)(2 * F) * H; // rows [2F, 3F)

        ull accA[4] = {0, 0, 0, 0};
        ull accC[4] = {0, 0, 0, 0};

        #pragma unroll 4
        for (int f = 0; f < F; f++) {
            float wa = W1a[f * H + h];               // coalesced LDG
            float wc = W1c[f * H + h];
            ull wa2 = pack2(wa, wa);
            ull wc2 = pack2(wc, wc);
            ull v0 = rxu[f * 4 + 0];                 // LDS.64 broadcast
            ull v1 = rxu[f * 4 + 1];
            ull v2 = rxu[f * 4 + 2];
            ull v3 = rxu[f * 4 + 3];
            accA[0] = fma2(v0, wa2, accA[0]);
            accA[1] = fma2(v1, wa2, accA[1]);
            accA[2] = fma2(v2, wa2, accA[2]);
            accA[3] = fma2(v3, wa2, accA[3]);
            accC[0] = fma2(v0, wc2, accC[0]);
            accC[1] = fma2(v1, wc2, accC[1]);
            accC[2] = fma2(v2, wc2, accC[2]);
            accC[3] = fma2(v3, wc2, accC[3]);
        }

        #pragma unroll
        for (int p = 0; p < 4; p++) {
            float a0, a1, c0, c1;
            unpack2(accA[p], a0, a1);
            unpack2(accC[p], c0, c1);
            g_A[(row0 + 2 * p) * H + h]     = a0;
            g_A[(row0 + 2 * p + 1) * H + h] = a1;
            g_C[(row0 + 2 * p) * H + h]     = c0;
            g_C[(row0 + 2 * p + 1) * H + h] = c1;
        }
    } else {
        // ================== pool: mean -> @Wp -> relu -> @W1p + b1 ==========
        int b = blockIdx.x - 128;
        float* part2 = sbuf;            // [2][F]
        float* m     = sbuf + 256;      // [F]
        float* r     = sbuf + 384;      // [F]
        const float* xb = x + b * N * F;

        // Phase 1: column mean (2 groups x 128 nodes)
        {
            int f = tid & (F - 1);
            int g = tid >> 7;
            float s = 0.f;
            #pragma unroll 16
            for (int n = 0; n < 128; n++)
                s += xb[(g * 128 + n) * F + f];
            part2[g * F + f] = s;
        }
        __syncthreads();
        if (tid < F) m[tid] = (part2[tid] + part2[F + tid]) * (1.0f / N);
        __syncthreads();

        // Phase 2: hp[f] = relu(sum m[fin] * Wp[fin, f])  (2 groups x 64)
        {
            int f = tid & (F - 1);
            int g = tid >> 7;
            float s = 0.f;
            #pragma unroll 16
            for (int k = 0; k < 64; k++) {
                int fin = g * 64 + k;
                s += m[fin] * Wp[fin * F + f];
            }
            part2[g * F + f] = s;
        }
        __syncthreads();
        if (tid < F) r[tid] = fmaxf(part2[tid] + part2[F + tid], 0.f);
        __syncthreads();

        // Phase 3: u[h] = sum_f r[f] * W1[f, h] + b1[h]  (1 thread per h)
        {
            int h = tid;
            float s = 0.f;
            #pragma unroll 8
            for (int f = 0; f < F; f++)
                s += r[f] * W1[f * H + h];
            g_ub[b * H + h] = s + b1[h];
        }
    }
}

// ---------------------------------------------------------------------------
// Kernel 2: pairwise fused readout.  grid(8,8,B), block(256)
//   32x32 output tile; thread computes 2x2 outputs (i,i+16)x(j,j+16).
//   H processed in 2 halves of 128 to fit static smem.
//   out[b,i,j] = sum_h relu(A[b,i,h] + ub[b,h] + C[b,j,h]) * W2[h] + b2
// ---------------------------------------------------------------------------
#define HS 128          // h per half
#define RSTR 130        // row stride in floats (even -> 8B aligned; %32==2
                        // so 16 distinct rows tile all 32 banks for LDS.64)

__global__ void __launch_bounds__(256) k_pair(
        const float* __restrict__ W2,
        const float* __restrict__ b2,
        float* __restrict__ out) {
    __shared__ __align__(16) float As[32 * RSTR];
    __shared__ __align__(16) float Cs[32 * RSTR];
    __shared__ __align__(16) float w2s[H];
    __shared__ __align__(16) float ubs[H];

    int b  = blockIdx.z;
    int i0 = blockIdx.y * 32;
    int j0 = blockIdx.x * 32;
    int tid = threadIdx.x;

    w2s[tid] = W2[tid];
    ubs[tid] = g_ub[b * H + tid];
    __syncthreads();   // ubs ready before fill reads it

    int tj = tid & 15;          // j-group
    int ti = tid >> 4;          // i-group (0..15)

    ull acc00 = 0, acc01 = 0, acc10 = 0, acc11 = 0;

    #pragma unroll
    for (int half = 0; half < 2; half++) {
        // ---- fill tiles: rows are (i0..i0+31), h-slice [half*128, +128) ----
        const float4* ub4 = (const float4*)(ubs + half * HS);
        for (int idx = tid; idx < 32 * 32; idx += 256) {
            int r  = idx >> 5;          // 0..31
            int qv = idx & 31;          // float4 index within 128 floats
            float4 a = ((const float4*)(g_A + ((size_t)(b * N + i0 + r)) * H + half * HS))[qv];
            float4 u = ub4[qv];
            float2* da = (float2*)(As + r * RSTR);
            da[2 * qv]     = make_float2(a.x + u.x, a.y + u.y);
            da[2 * qv + 1] = make_float2(a.z + u.z, a.w + u.w);
            float4 c = ((const float4*)(g_C + ((size_t)(b * N + j0 + r)) * H + half * HS))[qv];
            float2* dc = (float2*)(Cs + r * RSTR);
            dc[2 * qv]     = make_float2(c.x, c.y);
            dc[2 * qv + 1] = make_float2(c.z, c.w);
        }
        __syncthreads();

        // ---- compute: 64 h-pairs this half ----
        const ull* a0p = (const ull*)(As + ti * RSTR);
        const ull* a1p = (const ull*)(As + (ti + 16) * RSTR);
        const ull* c0p = (const ull*)(Cs + tj * RSTR);
        const ull* c1p = (const ull*)(Cs + (tj + 16) * RSTR);
        const ull* wp  = (const ull*)(w2s + half * HS);

        #pragma unroll 8
        for (int q = 0; q < HS / 2; q++) {
            ull a0 = a0p[q];
            ull a1 = a1p[q];
            ull c0 = c0p[q];
            ull c1 = c1p[q];
            ull w  = wp[q];
            acc00 = fma2(relu2(add2(a0, c0)), w, acc00);
            acc01 = fma2(relu2(add2(a0, c1)), w, acc01);
            acc10 = fma2(relu2(add2(a1, c0)), w, acc10);
            acc11 = fma2(relu2(add2(a1, c1)), w, acc11);
        }
        __syncthreads();
    }

    float b2v = b2[0];
    float lo, hi;
    size_t base = ((size_t)(b * N)) * N;
    unpack2(acc00, lo, hi);
    out[base + (size_t)(i0 + ti) * N + (j0 + tj)]           = lo + hi + b2v;
    unpack2(acc01, lo, hi);
    out[base + (size_t)(i0 + ti) * N + (j0 + tj + 16)]      = lo + hi + b2v;
    unpack2(acc10, lo, hi);
    out[base + (size_t)(i0 + ti + 16) * N + (j0 + tj)]      = lo + hi + b2v;
    unpack2(acc11, lo, hi);
    out[base + (size_t)(i0 + ti + 16) * N + (j0 + tj + 16)] = lo + hi + b2v;
}

// ---------------------------------------------------------------------------
extern "C" void kernel_launch(void* const* d_in, const int* in_sizes, int n_in,
                              void* d_out, int out_size) {
    const float* x   = (const float*)d_in[0];  // [B,N,F]
    const float* Wp  = (const float*)d_in[1];  // [F,F]
    const float* W1  = (const float*)d_in[2];  // [3F,H]
    const float* b1  = (const float*)d_in[3];  // [H]
    const float* W2  = (const float*)d_in[4];  // [H,1]
    const float* b2  = (const float*)d_in[5];  // [1]
    float* out = (float*)d_out;                // [B,N,N,1]

    k_main<<<132, 256>>>(x, Wp, W1, b1);
    k_pair<<<dim3(N / 32, N / 32, B), 256>>>(W2, b2, out);
}

// round 4
// speedup vs baseline: 2.5645x; 1.2465x over previous
#include <cuda_runtime.h>
#include <cuda_bf16.h>

// Problem constants
#define B 4
#define N 256
#define F 128
#define H 256

typedef unsigned long long ull;

// Scratch (allocation-free rule: __device__ globals)
__device__ __align__(16) float g_ub[B * H];     // u[b,h] + b1[h]
__device__ __align__(16) float g_A[B * N * H];  // relu(x_i) @ W1_i   (raw, no ub)
__device__ __align__(16) float g_C[B * N * H];  // relu(x_j) @ W1_j

// ---- packed f32x2 helpers (sm_100+) ---------------------------------------
static __device__ __forceinline__ ull add2(ull a, ull b) {
    ull d; asm("add.rn.f32x2 %0, %1, %2;" : "=l"(d) : "l"(a), "l"(b)); return d;
}
static __device__ __forceinline__ ull fma2(ull a, ull b, ull c) {
    ull d; asm("fma.rn.f32x2 %0, %1, %2, %3;" : "=l"(d) : "l"(a), "l"(b), "l"(c)); return d;
}
static __device__ __forceinline__ ull pack2(float lo, float hi) {
    ull d; asm("mov.b64 %0, {%1, %2};" : "=l"(d) : "f"(lo), "f"(hi)); return d;
}
static __device__ __forceinline__ void unpack2(ull v, float& lo, float& hi) {
    asm("mov.b64 {%0, %1}, %2;" : "=f"(lo), "=f"(hi) : "l"(v));
}
static __device__ __forceinline__ ull relu2(ull v) {
    float lo, hi; unpack2(v, lo, hi);
    return pack2(fmaxf(lo, 0.f), fmaxf(hi, 0.f));
}

// ---------------------------------------------------------------------------
// Kernel 1: fused nodegemm (blocks 0..127) + pool (blocks 128..131).
//   nodegemm: 8 rows per block, dual GEMM (A & C), W1 smem-staged with a
//   register double-buffer pipeline (16 chunks x 8 f).
// ---------------------------------------------------------------------------
#define CF 8          // f per chunk
#define NCHUNK (F / CF)

__global__ void __launch_bounds__(256) k_main(
        const float* __restrict__ x,
        const float* __restrict__ Wp,
        const float* __restrict__ W1,
        const float* __restrict__ b1) {
    __shared__ __align__(16) float rx[F * 8];              // [f][8 rows] 4 KB
    __shared__ __align__(16) float wbuf[2][CF][2][H];      // 32 KB staged W1a/W1c
    int tid = threadIdx.x;

    if (blockIdx.x < 128) {
        // ================== nodegemm ==================
        const int ROWS = 8;
        int row0 = blockIdx.x * ROWS;
        int h = tid;

        // rx packed: word f*8 + r  => row-pairs contiguous (8B)
        #pragma unroll
        for (int k = 0; k < 4; k++) {
            int idx = tid + k * 256;
            int r = idx >> 7, f = idx & (F - 1);
            rx[f * 8 + r] = fmaxf(x[(row0 + r) * F + f], 0.f);
        }

        // prologue: fetch chunk 0 and stage it
        float4 t0, t1, t2, t3;
        {
            #pragma unroll
            for (int k = 0; k < 4; k++) {
                int idx = tid + k * 256;            // 0..1023 float4s
                int part = idx >> 9;                // 0 = A-weights, 1 = C
                int rem = idx & 511;
                int fl = rem >> 6, q = rem & 63;
                float4 v = ((const float4*)(W1 + ((size_t)((1 + part) * F + fl)) * H))[q];
                if (k == 0) t0 = v; else if (k == 1) t1 = v;
                else if (k == 2) t2 = v; else t3 = v;
            }
            #pragma unroll
            for (int k = 0; k < 4; k++) {
                int idx = tid + k * 256;
                int part = idx >> 9;
                int rem = idx & 511;
                int fl = rem >> 6, q = rem & 63;
                float4 v = (k == 0) ? t0 : (k == 1) ? t1 : (k == 2) ? t2 : t3;
                ((float4*)&wbuf[0][fl][part][0])[q] = v;
            }
        }
        __syncthreads();

        const ull* rxu = (const ull*)rx;            // [F][4] row-pairs
        ull accA[4] = {0, 0, 0, 0};
        ull accC[4] = {0, 0, 0, 0};

        for (int c = 0; c < NCHUNK; c++) {
            int s = c & 1;
            bool pf = (c + 1) < NCHUNK;
            // prefetch next chunk into registers (LDG latency hidden by math)
            if (pf) {
                int fb = (c + 1) * CF;
                #pragma unroll
                for (int k = 0; k < 4; k++) {
                    int idx = tid + k * 256;
                    int part = idx >> 9;
                    int rem = idx & 511;
                    int fl = rem >> 6, q = rem & 63;
                    float4 v = ((const float4*)(W1 + ((size_t)((1 + part) * F + fb + fl)) * H))[q];
                    if (k == 0) t0 = v; else if (k == 1) t1 = v;
                    else if (k == 2) t2 = v; else t3 = v;
                }
            }
            // compute current chunk from smem
            #pragma unroll
            for (int fl = 0; fl < CF; fl++) {
                int f = c * CF + fl;
                float wa = wbuf[s][fl][0][h];
                float wc = wbuf[s][fl][1][h];
                ull wa2 = pack2(wa, wa);
                ull wc2 = pack2(wc, wc);
                ull v0 = rxu[f * 4 + 0];
                ull v1 = rxu[f * 4 + 1];
                ull v2 = rxu[f * 4 + 2];
                ull v3 = rxu[f * 4 + 3];
                accA[0] = fma2(v0, wa2, accA[0]);
                accA[1] = fma2(v1, wa2, accA[1]);
                accA[2] = fma2(v2, wa2, accA[2]);
                accA[3] = fma2(v3, wa2, accA[3]);
                accC[0] = fma2(v0, wc2, accC[0]);
                accC[1] = fma2(v1, wc2, accC[1]);
                accC[2] = fma2(v2, wc2, accC[2]);
                accC[3] = fma2(v3, wc2, accC[3]);
            }
            // stage prefetched chunk
            if (pf) {
                int ns = (c + 1) & 1;
                #pragma unroll
                for (int k = 0; k < 4; k++) {
                    int idx = tid + k * 256;
                    int part = idx >> 9;
                    int rem = idx & 511;
                    int fl = rem >> 6, q = rem & 63;
                    float4 v = (k == 0) ? t0 : (k == 1) ? t1 : (k == 2) ? t2 : t3;
                    ((float4*)&wbuf[ns][fl][part][0])[q] = v;
                }
            }
            __syncthreads();
        }

        #pragma unroll
        for (int p = 0; p < 4; p++) {
            float a0, a1, c0, c1;
            unpack2(accA[p], a0, a1);
            unpack2(accC[p], c0, c1);
            g_A[(row0 + 2 * p) * H + h]     = a0;
            g_A[(row0 + 2 * p + 1) * H + h] = a1;
            g_C[(row0 + 2 * p) * H + h]     = c0;
            g_C[(row0 + 2 * p + 1) * H + h] = c1;
        }
    } else {
        // ================== pool ==================
        int b = blockIdx.x - 128;
        float* part2 = rx;              // [2][F]
        float* m     = rx + 256;        // [F]
        float* r     = rx + 384;        // [F]
        const float* xb = x + b * N * F;

        // Phase 1: column mean (2 groups x 128 nodes, 4 indep accumulators)
        {
            int f = tid & (F - 1);
            int g = tid >> 7;
            const float* base = xb + g * 128 * F + f;
            float s0 = 0.f, s1 = 0.f, s2 = 0.f, s3 = 0.f;
            #pragma unroll
            for (int n = 0; n < 32; n++) {
                s0 += base[(n) * F];
                s1 += base[(n + 32) * F];
                s2 += base[(n + 64) * F];
                s3 += base[(n + 96) * F];
            }
            part2[g * F + f] = (s0 + s1) + (s2 + s3);
        }
        __syncthreads();
        if (tid < F) m[tid] = (part2[tid] + part2[F + tid]) * (1.0f / N);
        __syncthreads();

        // Phase 2: hp[f] = relu(sum m[fin] * Wp[fin, f])  (2 groups x 64)
        {
            int f = tid & (F - 1);
            int g = tid >> 7;
            float s0 = 0.f, s1 = 0.f;
            #pragma unroll
            for (int k = 0; k < 32; k++) {
                int fin = g * 64 + k;
                s0 += m[fin] * Wp[fin * F + f];
                s1 += m[fin + 32] * Wp[(fin + 32) * F + f];
            }
            part2[g * F + f] = s0 + s1;
        }
        __syncthreads();
        if (tid < F) r[tid] = fmaxf(part2[tid] + part2[F + tid], 0.f);
        __syncthreads();

        // Phase 3: u[h] = sum_f r[f] * W1[f, h] + b1[h]  (4 indep accums)
        {
            int h = tid;
            float s0 = 0.f, s1 = 0.f, s2 = 0.f, s3 = 0.f;
            #pragma unroll
            for (int f = 0; f < 32; f++) {
                s0 += r[f]      * W1[f * H + h];
                s1 += r[f + 32] * W1[(f + 32) * H + h];
                s2 += r[f + 64] * W1[(f + 64) * H + h];
                s3 += r[f + 96] * W1[(f + 96) * H + h];
            }
            g_ub[b * H + h] = (s0 + s1) + (s2 + s3) + b1[h];
        }
    }
}

// ---------------------------------------------------------------------------
// Kernel 2: pairwise fused readout.  grid(8,8,B), block(128)
//   32x32 output tile; thread computes 4x2 outputs: rows ti+{0,8,16,24},
//   cols tj+{0,16}.  H processed in 4 quarters of 64.
//   out[b,i,j] = sum_h relu(A[b,i,h]+ub[b,h] + C[b,j,h]) * W2[h] + b2
// ---------------------------------------------------------------------------
#define HS 64           // h per quarter
#define RQ 66           // row stride in floats (66%32==2: conflict-free LDS.64)
#define RQU 33          // row stride in ull

__global__ void __launch_bounds__(128) k_pair(
        const float* __restrict__ W2,
        const float* __restrict__ b2,
        float* __restrict__ out) {
    __shared__ __align__(16) float As[32 * RQ];
    __shared__ __align__(16) float Cs[32 * RQ];
    __shared__ __align__(16) float w2s[H];
    __shared__ __align__(16) float ubs[H];

    int b  = blockIdx.z;
    int i0 = blockIdx.y * 32;
    int j0 = blockIdx.x * 32;
    int tid = threadIdx.x;

    w2s[tid] = W2[tid];
    w2s[tid + 128] = W2[tid + 128];
    ubs[tid] = g_ub[b * H + tid];
    ubs[tid + 128] = g_ub[b * H + tid + 128];
    __syncthreads();

    int tj = tid & 15;          // j-group: cols tj, tj+16
    int ti = tid >> 4;          // i-group (0..7): rows ti, ti+8, ti+16, ti+24

    ull acc00 = 0, acc01 = 0;   // row ti
    ull acc10 = 0, acc11 = 0;   // row ti+8
    ull acc20 = 0, acc21 = 0;   // row ti+16
    ull acc30 = 0, acc31 = 0;   // row ti+24

    #pragma unroll
    for (int quarter = 0; quarter < 4; quarter++) {
        int ho = quarter * HS;
        // ---- fill tiles (ub folded into A) ----
        #pragma unroll
        for (int k = 0; k < 4; k++) {
            int idx = tid + k * 128;        // 0..511: r = idx>>4, q = idx&15
            int r = idx >> 4, q = idx & 15;
            float4 a = ((const float4*)(g_A + ((size_t)(b * N + i0 + r)) * H + ho))[q];
            float4 u = ((const float4*)(ubs + ho))[q];
            float2* da = (float2*)(As + r * RQ + 4 * q);
            da[0] = make_float2(a.x + u.x, a.y + u.y);
            da[1] = make_float2(a.z + u.z, a.w + u.w);
            float4 c = ((const float4*)(g_C + ((size_t)(b * N + j0 + r)) * H + ho))[q];
            float2* dc = (float2*)(Cs + r * RQ + 4 * q);
            dc[0] = make_float2(c.x, c.y);
            dc[1] = make_float2(c.z, c.w);
        }
        __syncthreads();

        // ---- compute: 32 h-pairs this quarter ----
        const ull* a0p = (const ull*)As + (size_t)ti * RQU;
        const ull* a1p = a0p + 8 * RQU;
        const ull* a2p = a0p + 16 * RQU;
        const ull* a3p = a0p + 24 * RQU;
        const ull* c0p = (const ull*)Cs + (size_t)tj * RQU;
        const ull* c1p = c0p + 16 * RQU;
        const ull* wp  = (const ull*)(w2s + ho);

        #pragma unroll 8
        for (int q = 0; q < HS / 2; q++) {
            ull a0 = a0p[q];
            ull a1 = a1p[q];
            ull a2 = a2p[q];
            ull a3 = a3p[q];
            ull c0 = c0p[q];
            ull c1 = c1p[q];
            ull w  = wp[q];
            acc00 = fma2(relu2(add2(a0, c0)), w, acc00);
            acc01 = fma2(relu2(add2(a0, c1)), w, acc01);
            acc10 = fma2(relu2(add2(a1, c0)), w, acc10);
            acc11 = fma2(relu2(add2(a1, c1)), w, acc11);
            acc20 = fma2(relu2(add2(a2, c0)), w, acc20);
            acc21 = fma2(relu2(add2(a2, c1)), w, acc21);
            acc30 = fma2(relu2(add2(a3, c0)), w, acc30);
            acc31 = fma2(relu2(add2(a3, c1)), w, acc31);
        }
        __syncthreads();
    }

    float b2v = b2[0];
    size_t base = ((size_t)(b * N)) * N;
    float lo, hi;
    #pragma unroll
    for (int k = 0; k < 4; k++) {
        ull v0 = (k == 0) ? acc00 : (k == 1) ? acc10 : (k == 2) ? acc20 : acc30;
        ull v1 = (k == 0) ? acc01 : (k == 1) ? acc11 : (k == 2) ? acc21 : acc31;
        size_t row = base + (size_t)(i0 + ti + 8 * k) * N;
        unpack2(v0, lo, hi);
        out[row + (j0 + tj)]      = lo + hi + b2v;
        unpack2(v1, lo, hi);
        out[row + (j0 + tj + 16)] = lo + hi + b2v;
    }
}

// ---------------------------------------------------------------------------
extern "C" void kernel_launch(void* const* d_in, const int* in_sizes, int n_in,
                              void* d_out, int out_size) {
    const float* x   = (const float*)d_in[0];  // [B,N,F]
    const float* Wp  = (const float*)d_in[1];  // [F,F]
    const float* W1  = (const float*)d_in[2];  // [3F,H]
    const float* b1  = (const float*)d_in[3];  // [H]
    const float* W2  = (const float*)d_in[4];  // [H,1]
    const float* b2  = (const float*)d_in[5];  // [1]
    float* out = (float*)d_out;                // [B,N,N,1]

    k_main<<<132, 256>>>(x, Wp, W1, b1);
    k_pair<<<dim3(N / 32, N / 32, B), 128>>>(W2, b2, out);
}

// round 5
// speedup vs baseline: 2.7582x; 1.0755x over previous
#include <cuda_runtime.h>
#include <cuda_bf16.h>

// Problem constants
#define B 4
#define N 256
#define F 128
#define H 256

typedef unsigned long long ull;

// Scratch (allocation-free rule: __device__ globals)
__device__ __align__(16) float g_ub[B * H];     // u[b,h] + b1[h]
__device__ __align__(16) float g_A[B * N * H];  // relu(x_i) @ W1_i   (raw, no ub)
__device__ __align__(16) float g_C[B * N * H];  // relu(x_j) @ W1_j

// ---- packed f32x2 helpers (sm_100+) ---------------------------------------
static __device__ __forceinline__ ull add2(ull a, ull b) {
    ull d; asm("add.rn.f32x2 %0, %1, %2;" : "=l"(d) : "l"(a), "l"(b)); return d;
}
static __device__ __forceinline__ ull fma2(ull a, ull b, ull c) {
    ull d; asm("fma.rn.f32x2 %0, %1, %2, %3;" : "=l"(d) : "l"(a), "l"(b), "l"(c)); return d;
}
static __device__ __forceinline__ ull pack2(float lo, float hi) {
    ull d; asm("mov.b64 %0, {%1, %2};" : "=l"(d) : "f"(lo), "f"(hi)); return d;
}
static __device__ __forceinline__ void unpack2(ull v, float& lo, float& hi) {
    asm("mov.b64 {%0, %1}, %2;" : "=f"(lo), "=f"(hi) : "l"(v));
}
static __device__ __forceinline__ ull relu2(ull v) {
    float lo, hi; unpack2(v, lo, hi);
    return pack2(fmaxf(lo, 0.f), fmaxf(hi, 0.f));
}
static __device__ __forceinline__ float hsum2(ull v) {
    float lo, hi; unpack2(v, lo, hi); return lo + hi;
}

// ---------------------------------------------------------------------------
// Kernel 1: fused nodegemm (blocks 0..127) + pool (blocks 128..131).
//   nodegemm blocks are (row-group of 16 rows) x (h-half of 128):
//   halves the W1 L2 traffic per row covered (32MB -> 16MB total).
// ---------------------------------------------------------------------------
#define CF 16         // f per chunk
#define NCHUNK (F / CF)
#define HW 128        // h per gemm block

__global__ void __launch_bounds__(256) k_main(
        const float* __restrict__ x,
        const float* __restrict__ Wp,
        const float* __restrict__ W1,
        const float* __restrict__ b1) {
    __shared__ __align__(16) float rx[F * 16];             // [f][16 rows] 8 KB
    __shared__ __align__(16) float wbuf[2][CF][2][HW];     // 32 KB staged W1a/W1c
    int tid = threadIdx.x;

    if (blockIdx.x < 128) {
        // ================== nodegemm ==================
        int row0 = (blockIdx.x >> 1) * 16;     // 16 rows per block
        int h0   = (blockIdx.x & 1) * HW;      // h-half
        int hl = tid & (HW - 1);               // 0..127
        int rg = tid >> 7;                     // 0..1 -> rows rg*8..rg*8+7

        // rx packed: word f*16 + r  => row-pairs contiguous (8B)
        #pragma unroll
        for (int k = 0; k < 8; k++) {
            int idx = tid + k * 256;
            int r = idx >> 7, f = idx & (F - 1);
            rx[f * 16 + r] = fmaxf(x[(row0 + r) * F + f], 0.f);
        }

        const float* W1base = W1 + (size_t)F * H + h0;  // rows [F,3F), this h-half

        // prologue: fetch chunk 0 and stage it
        float4 t0, t1, t2, t3;
        {
            #pragma unroll
            for (int k = 0; k < 4; k++) {
                int idx = tid + k * 256;            // 0..1023 float4s
                int part = idx >> 9;                // 0 = A-weights, 1 = C
                int rem = idx & 511;
                int fl = rem >> 5, q = rem & 31;
                float4 v = ((const float4*)(W1base + ((size_t)(part * F + fl)) * H))[q];
                if (k == 0) t0 = v; else if (k == 1) t1 = v;
                else if (k == 2) t2 = v; else t3 = v;
            }
            #pragma unroll
            for (int k = 0; k < 4; k++) {
                int idx = tid + k * 256;
                int part = idx >> 9;
                int rem = idx & 511;
                int fl = rem >> 5, q = rem & 31;
                float4 v = (k == 0) ? t0 : (k == 1) ? t1 : (k == 2) ? t2 : t3;
                ((float4*)&wbuf[0][fl][part][0])[q] = v;
            }
        }
        __syncthreads();

        const ull* rxu = (const ull*)rx;            // [F][8] row-pairs
        ull accA[4] = {0, 0, 0, 0};
        ull accC[4] = {0, 0, 0, 0};

        for (int c = 0; c < NCHUNK; c++) {
            int s = c & 1;
            bool pf = (c + 1) < NCHUNK;
            // prefetch next chunk into registers
            if (pf) {
                int fb = (c + 1) * CF;
                #pragma unroll
                for (int k = 0; k < 4; k++) {
                    int idx = tid + k * 256;
                    int part = idx >> 9;
                    int rem = idx & 511;
                    int fl = rem >> 5, q = rem & 31;
                    float4 v = ((const float4*)(W1base + ((size_t)(part * F + fb + fl)) * H))[q];
                    if (k == 0) t0 = v; else if (k == 1) t1 = v;
                    else if (k == 2) t2 = v; else t3 = v;
                }
            }
            // compute current chunk from smem
            #pragma unroll
            for (int fl = 0; fl < CF; fl++) {
                int f = c * CF + fl;
                float wa = wbuf[s][fl][0][hl];
                float wc = wbuf[s][fl][1][hl];
                ull wa2 = pack2(wa, wa);
                ull wc2 = pack2(wc, wc);
                ull v0 = rxu[f * 8 + rg * 4 + 0];   // broadcast within rg-group
                ull v1 = rxu[f * 8 + rg * 4 + 1];
                ull v2 = rxu[f * 8 + rg * 4 + 2];
                ull v3 = rxu[f * 8 + rg * 4 + 3];
                accA[0] = fma2(v0, wa2, accA[0]);
                accA[1] = fma2(v1, wa2, accA[1]);
                accA[2] = fma2(v2, wa2, accA[2]);
                accA[3] = fma2(v3, wa2, accA[3]);
                accC[0] = fma2(v0, wc2, accC[0]);
                accC[1] = fma2(v1, wc2, accC[1]);
                accC[2] = fma2(v2, wc2, accC[2]);
                accC[3] = fma2(v3, wc2, accC[3]);
            }
            // stage prefetched chunk
            if (pf) {
                int ns = (c + 1) & 1;
                #pragma unroll
                for (int k = 0; k < 4; k++) {
                    int idx = tid + k * 256;
                    int part = idx >> 9;
                    int rem = idx & 511;
                    int fl = rem >> 5, q = rem & 31;
                    float4 v = (k == 0) ? t0 : (k == 1) ? t1 : (k == 2) ? t2 : t3;
                    ((float4*)&wbuf[ns][fl][part][0])[q] = v;
                }
            }
            __syncthreads();
        }

        #pragma unroll
        for (int p = 0; p < 4; p++) {
            int r0g = row0 + rg * 8 + 2 * p;
            float a0, a1, c0, c1;
            unpack2(accA[p], a0, a1);
            unpack2(accC[p], c0, c1);
            g_A[r0g * H + h0 + hl]       = a0;
            g_A[(r0g + 1) * H + h0 + hl] = a1;
            g_C[r0g * H + h0 + hl]       = c0;
            g_C[(r0g + 1) * H + h0 + hl] = c1;
        }
    } else {
        // ================== pool ==================
        int b = blockIdx.x - 128;
        float* part2 = rx;              // [2][F]
        float* m     = rx + 256;        // [F]
        float* r     = rx + 384;        // [F]
        const float* xb = x + b * N * F;

        // Phase 1: column mean (2 groups x 128 nodes, 4 indep accumulators)
        {
            int f = tid & (F - 1);
            int g = tid >> 7;
            const float* base = xb + g * 128 * F + f;
            float s0 = 0.f, s1 = 0.f, s2 = 0.f, s3 = 0.f;
            #pragma unroll
            for (int n = 0; n < 32; n++) {
                s0 += base[(n) * F];
                s1 += base[(n + 32) * F];
                s2 += base[(n + 64) * F];
                s3 += base[(n + 96) * F];
            }
            part2[g * F + f] = (s0 + s1) + (s2 + s3);
        }
        __syncthreads();
        if (tid < F) m[tid] = (part2[tid] + part2[F + tid]) * (1.0f / N);
        __syncthreads();

        // Phase 2: hp[f] = relu(sum m[fin] * Wp[fin, f])
        {
            int f = tid & (F - 1);
            int g = tid >> 7;
            float s0 = 0.f, s1 = 0.f;
            #pragma unroll
            for (int k = 0; k < 32; k++) {
                int fin = g * 64 + k;
                s0 += m[fin] * Wp[fin * F + f];
                s1 += m[fin + 32] * Wp[(fin + 32) * F + f];
            }
            part2[g * F + f] = s0 + s1;
        }
        __syncthreads();
        if (tid < F) r[tid] = fmaxf(part2[tid] + part2[F + tid], 0.f);
        __syncthreads();

        // Phase 3: u[h] = sum_f r[f] * W1[f, h] + b1[h]
        {
            int h = tid;
            float s0 = 0.f, s1 = 0.f, s2 = 0.f, s3 = 0.f;
            #pragma unroll
            for (int f = 0; f < 32; f++) {
                s0 += r[f]      * W1[f * H + h];
                s1 += r[f + 32] * W1[(f + 32) * H + h];
                s2 += r[f + 64] * W1[(f + 64) * H + h];
                s3 += r[f + 96] * W1[(f + 96) * H + h];
            }
            g_ub[b * H + h] = (s0 + s1) + (s2 + s3) + b1[h];
        }
    }
}

// ---------------------------------------------------------------------------
// Kernel 2: pairwise fused readout.  grid(8,8,B), block(256)
//   32x32 output tile; thread (tj, ti, hh) computes 4i x 2j partial sums over
//   its 128-h slice; 2-way smem reduction combines the hh halves.
//   H processed in 2 halves of 128 (smem tiles); within each half a thread
//   handles 64 h (its hh slice).
// ---------------------------------------------------------------------------
#define HS 128          // h per smem-resident half
#define RQ 130          // row stride in floats (130%32==2: conflict-free LDS.64)
#define RQU 65          // row stride in ull

__global__ void __launch_bounds__(256) k_pair(
        const float* __restrict__ W2,
        const float* __restrict__ b2,
        float* __restrict__ out) {
    __shared__ __align__(16) float As[32 * RQ];
    __shared__ __align__(16) float Cs[32 * RQ];
    __shared__ __align__(16) float w2s[H];
    __shared__ __align__(16) float ubs[H];
    __shared__ __align__(16) float psum[128][9];

    int b  = blockIdx.z;
    int i0 = blockIdx.y * 32;
    int j0 = blockIdx.x * 32;
    int tid = threadIdx.x;

    if (tid < 128) {
        w2s[tid] = W2[tid];
        w2s[tid + 128] = W2[tid + 128];
        ubs[tid] = g_ub[b * H + tid];
        ubs[tid + 128] = g_ub[b * H + tid + 128];
    }

    int tj = tid & 15;          // j-group: cols tj, tj+16
    int ti = (tid >> 4) & 7;    // i-group: rows ti, ti+8, ti+16, ti+24
    int hh = tid >> 7;          // h-slice within each half (0 or 1)

    ull acc00 = 0, acc01 = 0;   // row ti
    ull acc10 = 0, acc11 = 0;   // row ti+8
    ull acc20 = 0, acc21 = 0;   // row ti+16
    ull acc30 = 0, acc31 = 0;   // row ti+24

    #pragma unroll
    for (int half = 0; half < 2; half++) {
        int ho = half * HS;
        __syncthreads();        // (also covers w2s/ubs readiness on half 0)
        // ---- fill tiles (ub folded into A); 256 threads, 4+4 float4 each ----
        #pragma unroll
        for (int k = 0; k < 4; k++) {
            int idx = tid + k * 256;        // 0..1023: r = idx>>5, q = idx&31
            int r = idx >> 5, q = idx & 31;
            float4 a = ((const float4*)(g_A + ((size_t)(b * N + i0 + r)) * H + ho))[q];
            float4 u = ((const float4*)(ubs + ho))[q];
            float2* da = (float2*)(As + r * RQ + 4 * q);
            da[0] = make_float2(a.x + u.x, a.y + u.y);
            da[1] = make_float2(a.z + u.z, a.w + u.w);
            float4 c = ((const float4*)(g_C + ((size_t)(b * N + j0 + r)) * H + ho))[q];
            float2* dc = (float2*)(Cs + r * RQ + 4 * q);
            dc[0] = make_float2(c.x, c.y);
            dc[1] = make_float2(c.z, c.w);
        }
        __syncthreads();

        // ---- compute: this thread's 32 h-pairs of this half ----
        int hq = hh * 32;                    // ull offset within row
        const ull* a0p = (const ull*)As + (size_t)ti * RQU + hq;
        const ull* a1p = a0p + 8 * RQU;
        const ull* a2p = a0p + 16 * RQU;
        const ull* a3p = a0p + 24 * RQU;
        const ull* c0p = (const ull*)Cs + (size_t)tj * RQU + hq;
        const ull* c1p = c0p + 16 * RQU;
        const ull* wp  = (const ull*)(w2s + ho) + hq;

        #pragma unroll 8
        for (int q = 0; q < 32; q++) {
            ull a0 = a0p[q];
            ull a1 = a1p[q];
            ull a2 = a2p[q];
            ull a3 = a3p[q];
            ull c0 = c0p[q];
            ull c1 = c1p[q];
            ull w  = wp[q];
            acc00 = fma2(relu2(add2(a0, c0)), w, acc00);
            acc01 = fma2(relu2(add2(a0, c1)), w, acc01);
            acc10 = fma2(relu2(add2(a1, c0)), w, acc10);
            acc11 = fma2(relu2(add2(a1, c1)), w, acc11);
            acc20 = fma2(relu2(add2(a2, c0)), w, acc20);
            acc21 = fma2(relu2(add2(a2, c1)), w, acc21);
            acc30 = fma2(relu2(add2(a3, c0)), w, acc30);
            acc31 = fma2(relu2(add2(a3, c1)), w, acc31);
        }
    }

    // ---- reduce hh halves ----
    float v0 = hsum2(acc00), v1 = hsum2(acc01);
    float v2 = hsum2(acc10), v3 = hsum2(acc11);
    float v4 = hsum2(acc20), v5 = hsum2(acc21);
    float v6 = hsum2(acc30), v7 = hsum2(acc31);

    int p = tid & 127;
    if (hh == 1) {
        psum[p][0] = v0; psum[p][1] = v1; psum[p][2] = v2; psum[p][3] = v3;
        psum[p][4] = v4; psum[p][5] = v5; psum[p][6] = v6; psum[p][7] = v7;
    }
    __syncthreads();
    if (hh == 0) {
        float b2v = b2[0];
        v0 += psum[p][0]; v1 += psum[p][1]; v2 += psum[p][2]; v3 += psum[p][3];
        v4 += psum[p][4]; v5 += psum[p][5]; v6 += psum[p][6]; v7 += psum[p][7];
        size_t base = ((size_t)(b * N)) * N;
        size_t r0 = base + (size_t)(i0 + ti) * N + j0;
        out[r0 + tj]              = v0 + b2v;
        out[r0 + tj + 16]         = v1 + b2v;
        out[r0 + 8 * N + tj]      = v2 + b2v;
        out[r0 + 8 * N + tj + 16] = v3 + b2v;
        out[r0 + 16 * N + tj]      = v4 + b2v;
        out[r0 + 16 * N + tj + 16] = v5 + b2v;
        out[r0 + 24 * N + tj]      = v6 + b2v;
        out[r0 + 24 * N + tj + 16] = v7 + b2v;
    }
}

// ---------------------------------------------------------------------------
extern "C" void kernel_launch(void* const* d_in, const int* in_sizes, int n_in,
                              void* d_out, int out_size) {
    const float* x   = (const float*)d_in[0];  // [B,N,F]
    const float* Wp  = (const float*)d_in[1];  // [F,F]
    const float* W1  = (const float*)d_in[2];  // [3F,H]
    const float* b1  = (const float*)d_in[3];  // [H]
    const float* W2  = (const float*)d_in[4];  // [H,1]
    const float* b2  = (const float*)d_in[5];  // [1]
    float* out = (float*)d_out;                // [B,N,N,1]

    k_main<<<132, 256>>>(x, Wp, W1, b1);
    k_pair<<<dim3(N / 32, N / 32, B), 256>>>(W2, b2, out);
}